// round 1
// baseline (speedup 1.0000x reference)
#include <cuda_runtime.h>

#define DTC   0.001f
#define HID   512
#define NOUT  128
#define SEQL  2048
#define NB    64
#define MROWS (SEQL * NB)   // 131072 output rows, m = s*64 + b
#define NCH   (NB * NOUT)   // 8192 recurrence chains

// ---------------------------------------------------------------------------
// GEMM: z[m][o] = sum_h x[b,s,h] * W[o,h],  m = s*64+b  (so z is [seq,batch,out])
// Tile: 128 rows x 128 cols (all of N), K chunks of 16, double-buffered SMEM,
// 8x8 register micro-tile per thread (256 threads), 4+4 split in both dims.
// ---------------------------------------------------------------------------
__global__ __launch_bounds__(256, 2)
void snn_gemm(const float* __restrict__ x, const float* __restrict__ W,
              float* __restrict__ z) {
    // [k][row] layout, row stride 132 floats (528B = 33*16B, keeps float4 alignment)
    __shared__ __align__(16) float As[2][16][132];
    __shared__ __align__(16) float Bs[2][16][132];

    const int tid = threadIdx.x;
    const int m0  = blockIdx.x * 128;

    const int mq = (tid & 15) * 4;   // rows mq..mq+3 and mq+64..mq+67
    const int nq = (tid >> 4) * 4;   // cols nq..nq+3 and nq+64..nq+67

    // Global-load mapping: 512 float4 per 128x16 tile, 2 per thread.
    const int f0  = tid,        f1  = tid + 256;
    const int r0  = f0 >> 2,    r1  = f1 >> 2;       // row within tile
    const int k0o = (f0 & 3)*4, k1o = (f1 & 3)*4;    // k offset within chunk

    const int mA0 = m0 + r0, mA1 = m0 + r1;
    // x row for output row m: b = m & 63, s = m >> 6
    const float* gA0 = x + ((size_t)(mA0 & 63) * SEQL + (mA0 >> 6)) * HID + k0o;
    const float* gA1 = x + ((size_t)(mA1 & 63) * SEQL + (mA1 >> 6)) * HID + k1o;
    const float* gB0 = W + (size_t)r0 * HID + k0o;
    const float* gB1 = W + (size_t)r1 * HID + k1o;

    float acc[8][8];
#pragma unroll
    for (int i = 0; i < 8; i++)
#pragma unroll
        for (int j = 0; j < 8; j++) acc[i][j] = 0.f;

    // prologue: load chunk 0
    float4 ra0 = *(const float4*)(gA0);
    float4 ra1 = *(const float4*)(gA1);
    float4 rb0 = *(const float4*)(gB0);
    float4 rb1 = *(const float4*)(gB1);

    As[0][k0o+0][r0] = ra0.x; As[0][k0o+1][r0] = ra0.y;
    As[0][k0o+2][r0] = ra0.z; As[0][k0o+3][r0] = ra0.w;
    As[0][k1o+0][r1] = ra1.x; As[0][k1o+1][r1] = ra1.y;
    As[0][k1o+2][r1] = ra1.z; As[0][k1o+3][r1] = ra1.w;
    Bs[0][k0o+0][r0] = rb0.x; Bs[0][k0o+1][r0] = rb0.y;
    Bs[0][k0o+2][r0] = rb0.z; Bs[0][k0o+3][r0] = rb0.w;
    Bs[0][k1o+0][r1] = rb1.x; Bs[0][k1o+1][r1] = rb1.y;
    Bs[0][k1o+2][r1] = rb1.z; Bs[0][k1o+3][r1] = rb1.w;
    __syncthreads();

    int buf = 0;
    for (int kc = 16; kc <= HID; kc += 16) {
        const bool more = (kc < HID);
        if (more) {   // prefetch next chunk into registers
            ra0 = *(const float4*)(gA0 + kc);
            ra1 = *(const float4*)(gA1 + kc);
            rb0 = *(const float4*)(gB0 + kc);
            rb1 = *(const float4*)(gB1 + kc);
        }
        // consume current buffer
#pragma unroll
        for (int kk = 0; kk < 16; kk++) {
            float4 a0 = *(const float4*)&As[buf][kk][mq];
            float4 a1 = *(const float4*)&As[buf][kk][mq + 64];
            float4 b0 = *(const float4*)&Bs[buf][kk][nq];
            float4 b1 = *(const float4*)&Bs[buf][kk][nq + 64];
            float av[8] = {a0.x,a0.y,a0.z,a0.w, a1.x,a1.y,a1.z,a1.w};
            float bv[8] = {b0.x,b0.y,b0.z,b0.w, b1.x,b1.y,b1.z,b1.w};
#pragma unroll
            for (int ii = 0; ii < 8; ii++)
#pragma unroll
                for (int jj = 0; jj < 8; jj++)
                    acc[ii][jj] = fmaf(av[ii], bv[jj], acc[ii][jj]);
        }
        if (more) {
            buf ^= 1;
            As[buf][k0o+0][r0] = ra0.x; As[buf][k0o+1][r0] = ra0.y;
            As[buf][k0o+2][r0] = ra0.z; As[buf][k0o+3][r0] = ra0.w;
            As[buf][k1o+0][r1] = ra1.x; As[buf][k1o+1][r1] = ra1.y;
            As[buf][k1o+2][r1] = ra1.z; As[buf][k1o+3][r1] = ra1.w;
            Bs[buf][k0o+0][r0] = rb0.x; Bs[buf][k0o+1][r0] = rb0.y;
            Bs[buf][k0o+2][r0] = rb0.z; Bs[buf][k0o+3][r0] = rb0.w;
            Bs[buf][k1o+0][r1] = rb1.x; Bs[buf][k1o+1][r1] = rb1.y;
            Bs[buf][k1o+2][r1] = rb1.z; Bs[buf][k1o+3][r1] = rb1.w;
            __syncthreads();
        }
    }

    // epilogue: coalesced float4 stores, z is [m][128]
#pragma unroll
    for (int ii = 0; ii < 8; ii++) {
        const int row = m0 + mq + (ii & 3) + ((ii >> 2) << 6);
        float4 o0 = make_float4(acc[ii][0], acc[ii][1], acc[ii][2], acc[ii][3]);
        float4 o1 = make_float4(acc[ii][4], acc[ii][5], acc[ii][6], acc[ii][7]);
        *(float4*)&z[(size_t)row * NOUT + nq]      = o0;
        *(float4*)&z[(size_t)row * NOUT + nq + 64] = o1;
    }
}

// ---------------------------------------------------------------------------
// Scan: in-place over the z buffer (z[t][idx] is read, then overwritten by v[t]
// by the SAME thread — no cross-thread hazard). 8192 threads, one chain each.
// 4-group x 8-step software pipeline keeps ~24-32 loads in flight to hide L2/DRAM.
// ---------------------------------------------------------------------------
__global__ __launch_bounds__(256)
void snn_scan(float* __restrict__ zv, float* __restrict__ vf, float* __restrict__ iff,
              const float* __restrict__ tau_syn, const float* __restrict__ tau_mem,
              int write_finals) {
    const int idx = blockIdx.x * 256 + threadIdx.x;   // 0..8191  (= b*128 + o)
    const float tm = fminf(fmaxf(tau_mem[0], 0.f), 1.f);
    const float ts = fminf(fmaxf(tau_syn[0], 0.f), 1.f);
    const float A  = DTC * tm;   // dv coefficient
    const float B  = DTC * ts;   // i decay coefficient

    float* p = zv + idx;
    float v = 0.f, cur = 0.f;    // cur = synaptic current i

    float zb[4][8];
#pragma unroll
    for (int g = 0; g < 3; g++)
#pragma unroll
        for (int j = 0; j < 8; j++)
            zb[g][j] = p[(g * 8 + j) * NCH];

    for (int gg = 0; gg < 256; gg += 4) {
#pragma unroll
        for (int q = 0; q < 4; q++) {
            const int g  = gg + q;
            const int pg = g + 3;
            if (pg < 256) {
#pragma unroll
                for (int j = 0; j < 8; j++)
                    zb[(q + 3) & 3][j] = p[(pg * 8 + j) * NCH];
            }
#pragma unroll
            for (int j = 0; j < 8; j++) {
                const float zt = zb[q & 3][j];
                v = fmaf(A, cur - v, v);             // v += dt*tau_mem*(i - v)
                p[(g * 8 + j) * NCH] = v;            // voltages[t] = v_new
                cur = fmaf(-B, cur, cur) + zt;       // i = i - dt*tau_syn*i + z
            }
        }
    }

    if (write_finals) {
        vf[idx]  = v;
        iff[idx] = cur;
    }
}

// ---------------------------------------------------------------------------
extern "C" void kernel_launch(void* const* d_in, const int* in_sizes, int n_in,
                              void* d_out, int out_size) {
    // Robust input binding by element count: x=64*2048*512, W=128*512, 2 scalars
    const float* x  = nullptr;
    const float* W  = nullptr;
    const float* t_syn = nullptr;
    const float* t_mem = nullptr;
    for (int i = 0; i < n_in; i++) {
        if (in_sizes[i] == MROWS * HID)          x = (const float*)d_in[i];
        else if (in_sizes[i] == NOUT * HID)      W = (const float*)d_in[i];
        else if (in_sizes[i] == 1) {
            if (!t_syn) t_syn = (const float*)d_in[i];   // metadata order: tau_syn first
            else        t_mem = (const float*)d_in[i];
        }
    }

    float* out = (float*)d_out;
    const int vol = SEQL * NCH;                       // 16,777,216 voltage elements
    const int write_finals = (out_size >= vol + 2 * NCH) ? 1 : 0;

    // 1) GEMM writes z directly into the voltages region of d_out ([seq,batch,out])
    snn_gemm<<<MROWS / 128, 256>>>(x, W, out);
    // 2) In-place scan converts z -> voltages, appends final (v, i) if present
    snn_scan<<<NCH / 256, 256>>>(out, out + vol, out + vol + NCH,
                                 t_syn, t_mem, write_finals);
}

// round 3
// speedup vs baseline: 2.1669x; 2.1669x over previous
#include <cuda_runtime.h>
#include <cuda_bf16.h>
#include <cstdint>

#define DTC   0.001f
#define HID   512
#define NOUT  128
#define SEQL  2048
#define NB    64
#define MROWS (SEQL * NB)     // 131072 output rows, m = s*64 + b
#define NCH   (NB * NOUT)     // 8192 recurrence chains
#define SEG_P 32
#define SEG_L 64

// ---------------- scratch (no allocation allowed) ----------------
__device__ float g_segE_v[SEG_P * NCH];
__device__ float g_segE_i[SEG_P * NCH];
__device__ float g_init_v[SEG_P * NCH];
__device__ float g_init_i[SEG_P * NCH];

// ---------------- helpers ----------------
__device__ __forceinline__ uint32_t smem_u32(const void* p) {
    uint32_t a;
    asm("{ .reg .u64 t; cvta.to.shared.u64 t, %1; cvt.u32.u64 %0, t; }" : "=r"(a) : "l"(p));
    return a;
}
__device__ __forceinline__ uint32_t b2u(__nv_bfloat162 v) {
    return *reinterpret_cast<uint32_t*>(&v);
}
// split float4 into hi-bf16x4 and lo-bf16x4 packed words
__device__ __forceinline__ void split4(float4 f, uint2& h, uint2& l) {
    __nv_bfloat162 h0 = __floats2bfloat162_rn(f.x, f.y);
    __nv_bfloat162 h1 = __floats2bfloat162_rn(f.z, f.w);
    float lx = f.x - __bfloat162float(__low2bfloat16(h0));
    float ly = f.y - __bfloat162float(__high2bfloat16(h0));
    float lz = f.z - __bfloat162float(__low2bfloat16(h1));
    float lw = f.w - __bfloat162float(__high2bfloat16(h1));
    h.x = b2u(h0); h.y = b2u(h1);
    l.x = b2u(__floats2bfloat162_rn(lx, ly));
    l.y = b2u(__floats2bfloat162_rn(lz, lw));
}
__device__ __forceinline__ void ldsm_x4(uint32_t* r, uint32_t addr) {
    asm volatile("ldmatrix.sync.aligned.m8n8.x4.shared.b16 {%0,%1,%2,%3}, [%4];"
                 : "=r"(r[0]), "=r"(r[1]), "=r"(r[2]), "=r"(r[3]) : "r"(addr));
}
__device__ __forceinline__ void mma_bf16(float* c, const uint32_t* a,
                                         uint32_t b0, uint32_t b1) {
    asm volatile(
        "mma.sync.aligned.m16n8k16.row.col.f32.bf16.bf16.f32 "
        "{%0,%1,%2,%3}, {%4,%5,%6,%7}, {%8,%9}, {%0,%1,%2,%3};"
        : "+f"(c[0]), "+f"(c[1]), "+f"(c[2]), "+f"(c[3])
        : "r"(a[0]), "r"(a[1]), "r"(a[2]), "r"(a[3]), "r"(b0), "r"(b1));
}

// ---------------------------------------------------------------------------
// GEMM: z[m][o] = sum_h x[b,s,h]*W[o,h] via split-bf16 mma.sync (3 terms).
// CTA 128x128, BK=32 (16 chunks), double-buffered SMEM, 256 threads / 8 warps,
// warp tile 64x32. SMEM row = 32 bf16 (64B) padded to 80B -> conflict-free.
// ---------------------------------------------------------------------------
#define ROWB   80
#define MATB   (128 * ROWB)          // 10240 bytes per matrix
#define BUFB   (4 * MATB)            // Ah, Al, Bh, Bl
#define SMEMB  (2 * BUFB)            // 81920 bytes

extern __shared__ char dynsmem[];

__global__ __launch_bounds__(256, 1)
void snn_gemm_mma(const float* __restrict__ x, const float* __restrict__ W,
                  float* __restrict__ z) {
    const int tid  = threadIdx.x;
    const int wid  = tid >> 5;
    const int lane = tid & 31;
    const int m0   = blockIdx.x * 128;
    const int wm   = wid & 1;        // 2 M groups of 64
    const int wn   = wid >> 1;       // 4 N groups of 32

    const uint32_t sm = smem_u32(dynsmem);

    // ---- global load mapping: per pass, 32 rows x 8 float4 ----
    const int rA   = tid >> 3;       // 0..31
    const int colq = tid & 7;        // float4 index within 32-float row
    const float* pA[4];
    const float* pB[4];
#pragma unroll
    for (int p = 0; p < 4; p++) {
        const int row = p * 32 + rA;
        const int m = m0 + row;
        pA[p] = x + ((size_t)(m & 63) * SEQL + (size_t)(m >> 6)) * HID + colq * 4;
        pB[p] = W + (size_t)row * HID + colq * 4;
    }
    const uint32_t stoff = (uint32_t)rA * ROWB + (uint32_t)colq * 8;

    // ---- ldmatrix source addresses ----
    // A (16x16 x4): lanes 0-15 -> rows 0-15 (k lo 16B), lanes 16-31 -> +16B
    uint32_t aAddr[4];
#pragma unroll
    for (int i = 0; i < 4; i++) {
        const int arow = wm * 64 + i * 16 + (lane & 15);
        aAddr[i] = sm + (uint32_t)arow * ROWB + ((lane >> 4) & 1) * 16;
    }
    // B (x4 over two n8 tiles): q = lane>>3; row = nb + (q>>1)*8 + (lane&7); off = (q&1)*16
    uint32_t bAddr[2];
#pragma unroll
    for (int g = 0; g < 2; g++) {
        const int brow = wn * 32 + g * 16 + ((lane >> 4) & 1) * 8 + (lane & 7);
        bAddr[g] = sm + (uint32_t)(2 * MATB) + (uint32_t)brow * ROWB +
                   ((lane >> 3) & 1) * 16;
    }

    float acc[4][4][4];
#pragma unroll
    for (int i = 0; i < 4; i++)
#pragma unroll
        for (int j = 0; j < 4; j++)
#pragma unroll
            for (int q = 0; q < 4; q++) acc[i][j][q] = 0.f;

    float4 rgA[4], rgB[4];

    // ---- prologue: chunk 0 -> buf0; preload chunk1 regs ----
#pragma unroll
    for (int p = 0; p < 4; p++) { rgA[p] = *(const float4*)(pA[p]); rgB[p] = *(const float4*)(pB[p]); }
    {
        char* base = dynsmem;
#pragma unroll
        for (int p = 0; p < 4; p++) {
            uint2 h, l;
            const uint32_t o = stoff + (uint32_t)p * 32 * ROWB;
            split4(rgA[p], h, l);
            *(uint2*)(base + o) = h;
            *(uint2*)(base + MATB + o) = l;
            split4(rgB[p], h, l);
            *(uint2*)(base + 2 * MATB + o) = h;
            *(uint2*)(base + 3 * MATB + o) = l;
        }
    }
#pragma unroll
    for (int p = 0; p < 4; p++) { rgA[p] = *(const float4*)(pA[p] + 32); rgB[p] = *(const float4*)(pB[p] + 32); }
    __syncthreads();

    for (int c = 0; c < 16; c++) {
        const uint32_t bb = (uint32_t)(c & 1) * BUFB;

        // ---- compute on buffer (c&1): two k16 steps ----
#pragma unroll
        for (int ks = 0; ks < 2; ks++) {
            const uint32_t ko = (uint32_t)ks * 32;
            uint32_t ah[4][4], al[4][4];
#pragma unroll
            for (int i = 0; i < 4; i++) {
                ldsm_x4(ah[i], aAddr[i] + bb + ko);
                ldsm_x4(al[i], aAddr[i] + bb + ko + MATB);
            }
            uint32_t bh[8], bl[8];
            ldsm_x4(bh + 0, bAddr[0] + bb + ko);
            ldsm_x4(bh + 4, bAddr[1] + bb + ko);
            ldsm_x4(bl + 0, bAddr[0] + bb + ko + MATB);
            ldsm_x4(bl + 4, bAddr[1] + bb + ko + MATB);
#pragma unroll
            for (int i = 0; i < 4; i++)
#pragma unroll
                for (int j = 0; j < 4; j++) {
                    mma_bf16(acc[i][j], ah[i], bh[2 * j], bh[2 * j + 1]);
                    mma_bf16(acc[i][j], ah[i], bl[2 * j], bl[2 * j + 1]);
                    mma_bf16(acc[i][j], al[i], bh[2 * j], bh[2 * j + 1]);
                }
        }

        if (c < 15) {
            __syncthreads();
            // store regs (chunk c+1) into buffer (c+1)&1
            char* base = dynsmem + ((c + 1) & 1) * BUFB;
#pragma unroll
            for (int p = 0; p < 4; p++) {
                uint2 h, l;
                const uint32_t o = stoff + (uint32_t)p * 32 * ROWB;
                split4(rgA[p], h, l);
                *(uint2*)(base + o) = h;
                *(uint2*)(base + MATB + o) = l;
                split4(rgB[p], h, l);
                *(uint2*)(base + 2 * MATB + o) = h;
                *(uint2*)(base + 3 * MATB + o) = l;
            }
            if (c < 14) {
                const int off = (c + 2) * 32;
#pragma unroll
                for (int p = 0; p < 4; p++) {
                    rgA[p] = *(const float4*)(pA[p] + off);
                    rgB[p] = *(const float4*)(pB[p] + off);
                }
            }
            __syncthreads();
        }
    }

    // ---- epilogue: acc -> z ----
    const int r0 = lane >> 2;
    const int c0 = (lane & 3) * 2;
#pragma unroll
    for (int i = 0; i < 4; i++) {
        const int mrow = m0 + wm * 64 + i * 16 + r0;
#pragma unroll
        for (int j = 0; j < 4; j++) {
            const int col = wn * 32 + j * 8 + c0;
            *(float2*)&z[(size_t)mrow * NOUT + col] =
                make_float2(acc[i][j][0], acc[i][j][1]);
            *(float2*)&z[(size_t)(mrow + 8) * NOUT + col] =
                make_float2(acc[i][j][2], acc[i][j][3]);
        }
    }
}

// ---------------------------------------------------------------------------
// Scan stage A: per (chain, segment) zero-state response; store end state.
// ---------------------------------------------------------------------------
__global__ __launch_bounds__(256)
void scan_segA(const float* __restrict__ zv,
               const float* __restrict__ tau_syn, const float* __restrict__ tau_mem) {
    const int t = blockIdx.x * 256 + threadIdx.x;
    const int chain = t & (NCH - 1);
    const int p = t >> 13;
    const float tm = fminf(fmaxf(tau_mem[0], 0.f), 1.f);
    const float ts = fminf(fmaxf(tau_syn[0], 0.f), 1.f);
    const float A = DTC * tm, B = DTC * ts;

    const float* zp = zv + (size_t)(p * SEG_L) * NCH + chain;
    float v = 0.f, cur = 0.f;
    float buf[8];
#pragma unroll
    for (int g = 0; g < SEG_L; g += 8) {
#pragma unroll
        for (int j = 0; j < 8; j++) buf[j] = zp[(g + j) * NCH];
#pragma unroll
        for (int j = 0; j < 8; j++) {
            v = fmaf(A, cur - v, v);
            cur = fmaf(-B, cur, cur) + buf[j];
        }
    }
    g_segE_v[t] = v;
    g_segE_i[t] = cur;
}

// ---------------------------------------------------------------------------
// Scan stage B: per chain, scan SEG_P segment summaries; store initial states.
// ---------------------------------------------------------------------------
__global__ __launch_bounds__(256)
void scan_segB(const float* __restrict__ tau_syn, const float* __restrict__ tau_mem) {
    const int chain = blockIdx.x * 256 + threadIdx.x;
    const float tm = fminf(fmaxf(tau_mem[0], 0.f), 1.f);
    const float ts = fminf(fmaxf(tau_syn[0], 0.f), 1.f);
    const float A = DTC * tm, B = DTC * ts;
    const float a = 1.f - A, b = 1.f - B;

    float pa = 1.f, pc = 0.f, pb = 1.f;   // M^SEG_L = [[pa,pc],[0,pb]]
#pragma unroll
    for (int k = 0; k < SEG_L; k++) {
        pc = a * pc + A * pb;
        pa = a * pa;
        pb = b * pb;
    }

    float v = 0.f, cur = 0.f;
#pragma unroll
    for (int p = 0; p < SEG_P; p++) {
        g_init_v[p * NCH + chain] = v;
        g_init_i[p * NCH + chain] = cur;
        const float ev = g_segE_v[p * NCH + chain];
        const float ei = g_segE_i[p * NCH + chain];
        const float nv = pa * v + pc * cur + ev;
        const float ni = pb * cur + ei;
        v = nv; cur = ni;
    }
}

// ---------------------------------------------------------------------------
// Scan stage C: exact per-segment recompute + in-place voltage write.
// ---------------------------------------------------------------------------
__global__ __launch_bounds__(256)
void scan_segC(float* __restrict__ zv, float* __restrict__ vf, float* __restrict__ iff,
               const float* __restrict__ tau_syn, const float* __restrict__ tau_mem,
               int write_finals) {
    const int t = blockIdx.x * 256 + threadIdx.x;
    const int chain = t & (NCH - 1);
    const int p = t >> 13;
    const float tm = fminf(fmaxf(tau_mem[0], 0.f), 1.f);
    const float ts = fminf(fmaxf(tau_syn[0], 0.f), 1.f);
    const float A = DTC * tm, B = DTC * ts;

    float v = g_init_v[p * NCH + chain];
    float cur = g_init_i[p * NCH + chain];
    float* zp = zv + (size_t)(p * SEG_L) * NCH + chain;

    float buf[8];
#pragma unroll
    for (int g = 0; g < SEG_L; g += 8) {
#pragma unroll
        for (int j = 0; j < 8; j++) buf[j] = zp[(g + j) * NCH];
#pragma unroll
        for (int j = 0; j < 8; j++) {
            v = fmaf(A, cur - v, v);
            zp[(g + j) * NCH] = v;
            cur = fmaf(-B, cur, cur) + buf[j];
        }
    }
    if (write_finals && p == SEG_P - 1) {
        vf[chain] = v;
        iff[chain] = cur;
    }
}

// ---------------------------------------------------------------------------
extern "C" void kernel_launch(void* const* d_in, const int* in_sizes, int n_in,
                              void* d_out, int out_size) {
    const float* x = nullptr;
    const float* W = nullptr;
    const float* t_syn = nullptr;
    const float* t_mem = nullptr;
    for (int i = 0; i < n_in; i++) {
        if (in_sizes[i] == MROWS * HID)     x = (const float*)d_in[i];
        else if (in_sizes[i] == NOUT * HID) W = (const float*)d_in[i];
        else if (in_sizes[i] == 1) {
            if (!t_syn) t_syn = (const float*)d_in[i];
            else        t_mem = (const float*)d_in[i];
        }
    }

    float* out = (float*)d_out;
    const int vol = SEQL * NCH;
    const int write_finals = (out_size >= vol + 2 * NCH) ? 1 : 0;

    static int smem_set = 0;
    if (!smem_set) {
        cudaFuncSetAttribute(snn_gemm_mma,
                             cudaFuncAttributeMaxDynamicSharedMemorySize, SMEMB);
        smem_set = 1;
    }

    snn_gemm_mma<<<MROWS / 128, 256, SMEMB>>>(x, W, out);
    scan_segA<<<(SEG_P * NCH) / 256, 256>>>(out, t_syn, t_mem);
    scan_segB<<<NCH / 256, 256>>>(t_syn, t_mem);
    scan_segC<<<(SEG_P * NCH) / 256, 256>>>(out, out + vol, out + vol + NCH,
                                            t_syn, t_mem, write_finals);
}